// round 11
// baseline (speedup 1.0000x reference)
#include <cuda_runtime.h>
#include <cuda_bf16.h>
#include <cstdint>

// NCEAverage: out[b,k] = exp(dot(memory[idx'[b,k]], x[b]) / T) / Z
// idx'[b,0] = y[b];  Z = mean(out_unnorm) * N
// B=256, K=4096, D=128, N=1e6, T=0.07
//
// Phase-partitioned gather (4 phases — empirically optimal): 512 blocks
// (single resident wave) each own one (b, 2048-k) range and deterministically
// bucket their 2048 row indices by row>>18; the chip sweeps phases roughly
// together so duplicate rows hit L2 instead of DRAM. Scores staged in SMEM,
// flushed with plain stores (out stays L2-resident for the norm kernel).
// Norm kernel launched with PDL so its dispatch overlaps the scores tail.
// Z: ticket + last-block fixed-order double reduce (deterministic).

#define B_SZ 256
#define K_SZ 4096
#define D_SZ 128
#define N_SZ 1000000
#define INV_T (1.0f / 0.07f)

#define TPB 256
#define WARPS 8
#define KRANGE 2048                    // k's per block
#define NBLK (B_SZ * K_SZ / KRANGE)    // 512 blocks = one resident wave
#define EPT (KRANGE / TPB)             // 8 indices per thread
#define PHASE_SHIFT 18                 // 4 phases of <=262144 rows (~134MB)

__device__ float        g_partials[NBLK];
__device__ float        g_scale;
__device__ unsigned int g_ticket;      // zero-init; last block resets

__global__ __launch_bounds__(TPB, 4)
void nce_scores_kernel(const float* __restrict__ x,
                       const int* __restrict__ y,
                       const int* __restrict__ idx,
                       const float* __restrict__ memory,
                       float* __restrict__ out) {
    __shared__ uint32_t           entries[KRANGE];   // (row<<11)|k_local
    __shared__ float              sout[KRANGE];      // staged scores
    __shared__ unsigned long long wtot[WARPS];
    __shared__ float              ssum[WARPS];
    __shared__ double             dsh[TPB];
    __shared__ bool               s_last;

    const int t     = threadIdx.x;
    const int lane  = t & 31;
    const int warp  = t >> 5;
    const int o     = lane & 7;        // octet within row
    const int r     = lane >> 3;       // which of 4 rows in a group
    const int b     = blockIdx.x >> 1;
    const int kbase = (blockIdx.x & 1) * KRANGE;

    // ---- 1. Load indices, count per phase (thread-major canonical order) ----
    const int* idx_b = idx + (size_t)b * K_SZ + kbase;
    uint32_t myrow[EPT];
    uint32_t c0 = 0, c1 = 0, c2 = 0, c3 = 0;
    #pragma unroll
    for (int j = 0; j < EPT; j++) {
        const int kl = j * TPB + t;
        const uint32_t row = (uint32_t)((kbase + kl == 0) ? y[b] : idx_b[kl]);
        myrow[j] = row;
        const uint32_t p = row >> PHASE_SHIFT;
        c0 += (p == 0); c1 += (p == 1); c2 += (p == 2); c3 += (p == 3);
    }

    // ---- 2. Scan of 4x16-bit packed counts: warp shfl scan + cross-warp ----
    const unsigned long long v = (unsigned long long)c0
                               | ((unsigned long long)c1 << 16)
                               | ((unsigned long long)c2 << 32)
                               | ((unsigned long long)c3 << 48);
    unsigned long long ws = v;                       // warp-inclusive scan
    #pragma unroll
    for (int off = 1; off < 32; off <<= 1) {
        const unsigned long long n = __shfl_up_sync(0xffffffffu, ws, off);
        if (lane >= off) ws += n;
    }
    if (lane == 31) wtot[warp] = ws;
    __syncthreads();
    unsigned long long wpre = 0, tot = 0;
    #pragma unroll
    for (int w = 0; w < WARPS; w++) {               // fixed order, tiny
        const unsigned long long wv = wtot[w];
        if (w < warp) wpre += wv;
        tot += wv;
    }
    const unsigned long long incl = ws + wpre;
    const unsigned long long excl = incl - v;

    const uint32_t t0 = (uint32_t)(tot      ) & 0xffffu;
    const uint32_t t1 = (uint32_t)(tot >> 16) & 0xffffu;
    const uint32_t t2 = (uint32_t)(tot >> 32) & 0xffffu;
    const uint32_t t3 = (uint32_t)(tot >> 48) & 0xffffu;

    uint32_t pos0 =                ((uint32_t)(excl      ) & 0xffffu);
    uint32_t pos1 = t0           + ((uint32_t)(excl >> 16) & 0xffffu);
    uint32_t pos2 = t0 + t1      + ((uint32_t)(excl >> 32) & 0xffffu);
    uint32_t pos3 = t0 + t1 + t2 + ((uint32_t)(excl >> 48) & 0xffffu);

    // ---- 3. Deterministic scatter into phase buckets ----
    #pragma unroll
    for (int j = 0; j < EPT; j++) {
        const uint32_t row = myrow[j];
        const uint32_t p   = row >> PHASE_SHIFT;
        const uint32_t ent = (row << 11) | (uint32_t)(j * TPB + t);
        uint32_t pp;
        if      (p == 0) pp = pos0++;
        else if (p == 1) pp = pos1++;
        else if (p == 2) pp = pos2++;
        else             pp = pos3++;
        entries[pp] = ent;
    }
    __syncthreads();

    // ---- 4. Gather + dot + exp, phase by phase ----
    const float4* x4 = reinterpret_cast<const float4*>(x + b * D_SZ);
    const float4 xx0 = x4[0 * 8 + o];
    const float4 xx1 = x4[1 * 8 + o];
    const float4 xx2 = x4[2 * 8 + o];
    const float4 xx3 = x4[3 * 8 + o];

    const uint32_t tc[4] = { t0, t1, t2, t3 };
    float wsum = 0.0f;
    uint32_t lo = 0;
    #pragma unroll
    for (int p = 0; p < 4; p++) {
        const uint32_t hi = lo + tc[p];
        for (uint32_t e0 = lo + (uint32_t)warp * 4u; e0 < hi; e0 += WARPS * 4u) {
            const uint32_t e = e0 + (uint32_t)r;
            const bool valid = (e < hi);
            float acc = 0.0f;
            uint32_t kl = 0;
            if (valid) {
                const uint32_t ent = entries[e];
                const uint32_t row = ent >> 11;
                kl = ent & 2047u;
                const float4* m4 = reinterpret_cast<const float4*>(memory + (size_t)row * D_SZ);
                const float4 w0 = m4[0 * 8 + o];
                const float4 w1 = m4[1 * 8 + o];
                const float4 w2 = m4[2 * 8 + o];
                const float4 w3 = m4[3 * 8 + o];
                acc  = w0.x * xx0.x + w0.y * xx0.y + w0.z * xx0.z + w0.w * xx0.w;
                acc += w1.x * xx1.x + w1.y * xx1.y + w1.z * xx1.z + w1.w * xx1.w;
                acc += w2.x * xx2.x + w2.y * xx2.y + w2.z * xx2.z + w2.w * xx2.w;
                acc += w3.x * xx3.x + w3.y * xx3.y + w3.z * xx3.z + w3.w * xx3.w;
            }
            // converge, then reduce the 8 lanes of each row (4 rows at once)
            acc += __shfl_xor_sync(0xffffffffu, acc, 1);
            acc += __shfl_xor_sync(0xffffffffu, acc, 2);
            acc += __shfl_xor_sync(0xffffffffu, acc, 4);
            if (o == 0 && valid) {
                const float s = __expf(acc * INV_T);
                sout[kl] = s;
                wsum += s;
            }
        }
        lo = hi;
    }

    // ---- 5. Coalesced flush (plain stores: keep `out` L2-resident) ----
    __syncthreads();
    float4* ob4 = reinterpret_cast<float4*>(out + (size_t)b * K_SZ + kbase);
    const float4* so4 = reinterpret_cast<const float4*>(sout);
    #pragma unroll
    for (int i = 0; i < KRANGE / 4 / TPB; i++)      // 2 iterations
        ob4[t + i * TPB] = so4[t + i * TPB];

    // Allow the PDL secondary (norm) to begin dispatching; it still gates on
    // full completion of this grid via cudaGridDependencySynchronize().
    cudaTriggerProgrammaticLaunchCompletion();

    // ---- 6. Block partial (fixed order) + ticket ----
    #pragma unroll
    for (int s = 16; s > 0; s >>= 1)
        wsum += __shfl_xor_sync(0xffffffffu, wsum, s);
    if (lane == 0) ssum[warp] = wsum;
    __syncthreads();
    if (t == 0) {
        float acc = 0.0f;
        #pragma unroll
        for (int w = 0; w < WARPS; w++) acc += ssum[w];
        g_partials[blockIdx.x] = acc;
        __threadfence();
        const unsigned int tk = atomicAdd(&g_ticket, 1u);
        s_last = (tk == NBLK - 1);
    }
    __syncthreads();

    // ---- 7. Last block: fixed-order double reduce of 512 partials ----
    if (s_last) {
        double acc = (double)g_partials[t] + (double)g_partials[t + TPB];
        dsh[t] = acc;
        __syncthreads();
        for (int s = TPB / 2; s > 0; s >>= 1) {
            if (t < s) dsh[t] += dsh[t + s];
            __syncthreads();
        }
        if (t == 0) {
            // Z = (sum / (B*K)) * N ; scale = 1/Z — double avoids fp32
            // overflow (sum ~ 1e31; sum*N would be inf in fp32).
            const double sum = dsh[0];
            g_scale = (float)(((double)B_SZ * (double)K_SZ) /
                              (sum * (double)N_SZ));
            g_ticket = 0u;             // reset for graph replay
            __threadfence();
        }
    }
}

// out: 262144 float4s -> 1024 blocks x 256 threads x 1 float4.
// PDL secondary: blocks dispatch during scores' tail, gate on its completion.
__global__ __launch_bounds__(256)
void nce_norm_kernel(float* __restrict__ out) {
    cudaGridDependencySynchronize();   // scores grid done; g_scale visible
    const float s = g_scale;
    const int i = blockIdx.x * blockDim.x + threadIdx.x;
    float4* o = reinterpret_cast<float4*>(out);
    float4 v = o[i];
    v.x *= s; v.y *= s; v.z *= s; v.w *= s;
    __stcs(&o[i], v);
}

extern "C" void kernel_launch(void* const* d_in, const int* in_sizes, int n_in,
                              void* d_out, int out_size) {
    const float* x      = (const float*)d_in[0];
    const int*   y      = (const int*)d_in[1];
    const int*   idx    = (const int*)d_in[2];
    const float* memory = (const float*)d_in[3];
    float* out = (float*)d_out;

    nce_scores_kernel<<<NBLK, TPB>>>(x, y, idx, memory, out);

    // Norm with programmatic dependent launch (overlap dispatch with scores).
    cudaLaunchConfig_t cfg = {};
    cfg.gridDim  = dim3((B_SZ * K_SZ) / 4 / 256, 1, 1);   // 1024 blocks
    cfg.blockDim = dim3(256, 1, 1);
    cudaLaunchAttribute attrs[1];
    attrs[0].id = cudaLaunchAttributeProgrammaticStreamSerialization;
    attrs[0].val.programmaticStreamSerializationAllowed = 1;
    cfg.attrs = attrs;
    cfg.numAttrs = 1;
    cudaLaunchKernelEx(&cfg, nce_norm_kernel, out);
}